// round 2
// baseline (speedup 1.0000x reference)
#include <cuda_runtime.h>
#include <cuda_bf16.h>
#include <cstdint>

#define Nn 50000
#define Ee 800000
#define Hd 128
#define STB 200      // stats blocks
#define RPS 250      // rows per stats block (STB*RPS == Nn)

// ---------------- scratch ----------------
__device__ int   g_deg[Nn];
__device__ int   g_cnt[Nn];
__device__ int   g_rowptr[Nn + 1];
__device__ int   g_tmpptr[Nn];
__device__ float g_dinv[Nn];
__device__ int   g_csrc[Ee];
__device__ float g_cw[Ee];

__device__ __align__(256) float g_h[Nn * Hd];
__device__ __align__(256) float g_t1[Nn * Hd];
__device__ __align__(256) float g_t2[Nn * Hd];
__device__ __align__(256) float g_t3[Nn * Hd];
__device__ __align__(256) float g_out[Nn * Hd];

__device__ float g_s1[Nn * 3];
__device__ float g_s2[Nn * 3];
__device__ float g_s3[Nn * 3];

__device__ float g_part [STB * Hd];
__device__ float g_part2[STB * Hd];
__device__ float g_scale[Hd];
__device__ float g_shift[Hd];

// ---------------- graph build ----------------
__global__ void k_init() {
    int i = blockIdx.x * blockDim.x + threadIdx.x;
    if (i < Nn) { g_deg[i] = 0; g_cnt[i] = 0; }
}

// edge_index is int32 (JAX silently downgrades int64 without x64 enabled)
__global__ void k_count(const int* __restrict__ ei) {
    int e = blockIdx.x * blockDim.x + threadIdx.x;
    if (e < Ee) {
        int s = ei[e];
        int d = ei[e + Ee];
        if ((unsigned)s < Nn) atomicAdd(&g_deg[s], 1);   // out-degree by src
        if ((unsigned)d < Nn) atomicAdd(&g_cnt[d], 1);   // in-degree by dst (CSR)
    }
}

__global__ void k_dinv() {
    int i = blockIdx.x * blockDim.x + threadIdx.x;
    if (i < Nn) {
        int d = g_deg[i];
        g_dinv[i] = (d > 0) ? rsqrtf((float)d) : 0.0f;
    }
}

// single-block chunked inclusive scan of g_cnt -> g_rowptr / g_tmpptr
__global__ void k_scan() {
    __shared__ int sdata[1024];
    __shared__ int carry;
    int tid = threadIdx.x;
    if (tid == 0) { carry = 0; g_rowptr[0] = 0; }
    __syncthreads();
    for (int base = 0; base < Nn; base += 1024) {
        int i = base + tid;
        int v = (i < Nn) ? g_cnt[i] : 0;
        sdata[tid] = v;
        __syncthreads();
        for (int off = 1; off < 1024; off <<= 1) {
            int t = (tid >= off) ? sdata[tid - off] : 0;
            __syncthreads();
            sdata[tid] += t;
            __syncthreads();
        }
        int inc = sdata[tid];
        if (i < Nn) {
            g_rowptr[i + 1] = carry + inc;
            g_tmpptr[i]     = carry + inc - v;  // exclusive start
        }
        __syncthreads();
        if (tid == 1023) carry += sdata[1023];
        __syncthreads();
    }
}

__global__ void k_fill(const int* __restrict__ ei) {
    int e = blockIdx.x * blockDim.x + threadIdx.x;
    if (e < Ee) {
        int s = ei[e];
        int d = ei[e + Ee];
        if ((unsigned)s >= Nn || (unsigned)d >= Nn) return;
        int p = atomicAdd(&g_tmpptr[d], 1);
        g_csrc[p] = s;
        g_cw[p]   = -g_dinv[s] * g_dinv[d];
    }
}

// ---------------- propagation ----------------
__global__ void k_prop3(const float* __restrict__ hin,
                        const float* __restrict__ sub,
                        float* __restrict__ out) {
    int v = blockIdx.x * blockDim.x + threadIdx.x;
    if (v >= Nn) return;
    float a0 = 0.f, a1 = 0.f, a2 = 0.f;
    int b = g_rowptr[v], en = g_rowptr[v + 1];
    for (int i = b; i < en; i++) {
        int s = g_csrc[i];
        float w = g_cw[i];
        const float* hp = hin + s * 3;
        a0 += w * hp[0]; a1 += w * hp[1]; a2 += w * hp[2];
    }
    float* o = out + v * 3;
    if (sub) {
        const float* sv = sub + v * 3;
        o[0] = 2.f * a0 - sv[0]; o[1] = 2.f * a1 - sv[1]; o[2] = 2.f * a2 - sv[2];
    } else {
        o[0] = a0; o[1] = a1; o[2] = a2;
    }
}

// warp per node, float4 per lane, 4 warps per block
__global__ void k_prop128(const float* __restrict__ hin,
                          const float* __restrict__ sub,
                          float* __restrict__ out) {
    int v = blockIdx.x * 4 + (threadIdx.x >> 5);
    if (v >= Nn) return;
    int lane = threadIdx.x & 31;
    int b = g_rowptr[v], en = g_rowptr[v + 1];
    float4 acc = make_float4(0.f, 0.f, 0.f, 0.f);
    int i = b;
    for (; i + 1 < en; i += 2) {
        int   s0 = g_csrc[i];     float w0 = g_cw[i];
        int   s1 = g_csrc[i + 1]; float w1 = g_cw[i + 1];
        float4 v0 = *(const float4*)(hin + s0 * Hd + lane * 4);
        float4 v1 = *(const float4*)(hin + s1 * Hd + lane * 4);
        acc.x += w0 * v0.x + w1 * v1.x;
        acc.y += w0 * v0.y + w1 * v1.y;
        acc.z += w0 * v0.z + w1 * v1.z;
        acc.w += w0 * v0.w + w1 * v1.w;
    }
    if (i < en) {
        int s = g_csrc[i]; float w = g_cw[i];
        float4 g = *(const float4*)(hin + s * Hd + lane * 4);
        acc.x += w * g.x; acc.y += w * g.y; acc.z += w * g.z; acc.w += w * g.w;
    }
    float4 r;
    if (sub) {
        float4 sv = *(const float4*)(sub + v * Hd + lane * 4);
        r.x = 2.f * acc.x - sv.x; r.y = 2.f * acc.y - sv.y;
        r.z = 2.f * acc.z - sv.z; r.w = 2.f * acc.w - sv.w;
    } else {
        r = acc;
    }
    *(float4*)(out + v * Hd + lane * 4) = r;
}

// ---------------- layer 1 GEMM: K=12 ----------------
__global__ void k_gemm12(const float* __restrict__ x,  const float* __restrict__ t1,
                         const float* __restrict__ t2, const float* __restrict__ t3,
                         const float* __restrict__ W,  const float* __restrict__ bias,
                         float* __restrict__ out) {
    __shared__ float sW[12 * Hd];
    int c = threadIdx.x;
    #pragma unroll
    for (int j = 0; j < 12; j++) sW[j * Hd + c] = W[j * Hd + c];
    __syncthreads();
    const int RPB = 32;
    int v0 = blockIdx.x * RPB;
    float bv = bias[c];
    for (int r = 0; r < RPB; r++) {
        int v = v0 + r;
        if (v >= Nn) break;
        float a[12];
        #pragma unroll
        for (int f = 0; f < 3; f++) {
            a[f]     = x [v * 3 + f];
            a[3 + f] = t1[v * 3 + f];
            a[6 + f] = t2[v * 3 + f];
            a[9 + f] = t3[v * 3 + f];
        }
        float acc = bv;
        #pragma unroll
        for (int j = 0; j < 12; j++) acc += a[j] * sW[j * Hd + c];
        acc = (acc > 0.f) ? acc : 0.01f * acc;   // leaky relu
        out[v * Hd + c] = acc;
    }
}

// ---------------- main GEMM: M=Nn, K=512, N=128, fp32 ----------------
#define BM 128
#define BN 128
#define BK 16

__global__ __launch_bounds__(256)
void k_gemm512(const float* __restrict__ A0, const float* __restrict__ A1,
               const float* __restrict__ A2, const float* __restrict__ A3,
               const float* __restrict__ W,  const float* __restrict__ bias,
               float* __restrict__ out, int act) {
    __shared__ __align__(16) float As[BK][BM + 4];
    __shared__ __align__(16) float Bs[BK][BN];
    const float* Abuf[4] = {A0, A1, A2, A3};
    int tid = threadIdx.x;
    int tx = tid & 15, ty = tid >> 4;
    int row0 = blockIdx.x * BM;
    float acc[8][8];
    #pragma unroll
    for (int i = 0; i < 8; i++)
        #pragma unroll
        for (int j = 0; j < 8; j++) acc[i][j] = 0.f;

    for (int kt = 0; kt < 32; kt++) {
        const float* A = Abuf[kt >> 3];
        int cb = (kt & 7) * BK;
        #pragma unroll
        for (int l = 0; l < 2; l++) {
            int lid = tid + l * 256;
            int r = lid >> 2;
            int c4 = (lid & 3) * 4;
            int gr = row0 + r;
            float4 v = (gr < Nn) ? *(const float4*)(A + gr * Hd + cb + c4)
                                 : make_float4(0.f, 0.f, 0.f, 0.f);
            As[c4 + 0][r] = v.x; As[c4 + 1][r] = v.y;
            As[c4 + 2][r] = v.z; As[c4 + 3][r] = v.w;
        }
        #pragma unroll
        for (int l = 0; l < 2; l++) {
            int lid = tid + l * 256;
            int kk = lid >> 5;
            int c4 = (lid & 31) * 4;
            float4 v = *(const float4*)(W + (kt * BK + kk) * Hd + c4);
            *(float4*)&Bs[kk][c4] = v;
        }
        __syncthreads();
        #pragma unroll
        for (int kk = 0; kk < BK; kk++) {
            float ra[8], rb[8];
            #pragma unroll
            for (int i = 0; i < 8; i++) ra[i] = As[kk][ty + i * 16];
            #pragma unroll
            for (int j = 0; j < 8; j++) rb[j] = Bs[kk][tx + j * 16];
            #pragma unroll
            for (int i = 0; i < 8; i++)
                #pragma unroll
                for (int j = 0; j < 8; j++) acc[i][j] += ra[i] * rb[j];
        }
        __syncthreads();
    }
    #pragma unroll
    for (int j = 0; j < 8; j++) {
        int c = tx + j * 16;
        float bv = bias[c];
        #pragma unroll
        for (int i = 0; i < 8; i++) {
            int v = row0 + ty + i * 16;
            if (v < Nn) {
                float r = acc[i][j] + bv;
                if (act == 1) r = (r > 0.f) ? r : 0.01f * r;
                else if (act == 2) r = fmaxf(r, 0.f);
                out[v * Hd + c] = r;
            }
        }
    }
}

// ---------------- BN (deterministic two-stage) ----------------
__global__ void k_stats(const float* __restrict__ h) {
    int c = threadIdx.x;
    int b = blockIdx.x;
    float s = 0.f, s2 = 0.f;
    int v0 = b * RPS;
    for (int r = 0; r < RPS; r++) {
        float x = h[(v0 + r) * Hd + c];
        s += x; s2 += x * x;
    }
    g_part [b * Hd + c] = s;
    g_part2[b * Hd + c] = s2;
}

__global__ void k_bnfin(const float* __restrict__ gamma, const float* __restrict__ beta) {
    int c = threadIdx.x;
    float s = 0.f, s2 = 0.f;
    for (int b = 0; b < STB; b++) { s += g_part[b * Hd + c]; s2 += g_part2[b * Hd + c]; }
    float m   = s / (float)Nn;
    float var = s2 / (float)Nn - m * m;
    float inv = rsqrtf(var + 1e-5f);
    float sc  = gamma[c] * inv;
    g_scale[c] = sc;
    g_shift[c] = beta[c] - m * sc;
}

__global__ void k_bnapply(const float* __restrict__ in, float* __restrict__ outp) {
    int i = blockIdx.x * blockDim.x + threadIdx.x;   // over Nn*Hd/4 float4
    if (i < Nn * (Hd / 4)) {
        float4 v = ((const float4*)in)[i];
        int c = (i & (Hd / 4 - 1)) * 4;
        v.x = v.x * g_scale[c + 0] + g_shift[c + 0];
        v.y = v.y * g_scale[c + 1] + g_shift[c + 1];
        v.z = v.z * g_scale[c + 2] + g_shift[c + 2];
        v.w = v.w * g_scale[c + 3] + g_shift[c + 3];
        ((float4*)outp)[i] = v;
    }
}

// ---------------- final L2 row-normalize ----------------
__global__ void k_norm(const float* __restrict__ in, float* __restrict__ outp) {
    int v = blockIdx.x;
    int c = threadIdx.x;
    float x = in[v * Hd + c];
    float s = x * x;
    __shared__ float ws[4];
    #pragma unroll
    for (int o = 16; o; o >>= 1) s += __shfl_xor_sync(0xffffffffu, s, o);
    if ((c & 31) == 0) ws[c >> 5] = s;
    __syncthreads();
    float tot = ws[0] + ws[1] + ws[2] + ws[3];
    float nrm = fmaxf(sqrtf(tot), 1e-12f);
    outp[v * Hd + c] = x / nrm;
}

// ---------------- host ----------------
extern "C" void kernel_launch(void* const* d_in, const int* in_sizes, int n_in,
                              void* d_out, int out_size) {
    const float* x  = (const float*)d_in[0];
    const int*   ei = (const int*)d_in[1];   // int32 (JAX x64 disabled)
    const float* W1 = (const float*)d_in[2];  const float* b1 = (const float*)d_in[3];
    const float* W2 = (const float*)d_in[4];  const float* b2 = (const float*)d_in[5];
    const float* W3 = (const float*)d_in[6];  const float* b3 = (const float*)d_in[7];
    const float* W4 = (const float*)d_in[8];  const float* b4 = (const float*)d_in[9];
    const float* g1 = (const float*)d_in[10]; const float* be1 = (const float*)d_in[11];
    const float* g2 = (const float*)d_in[12]; const float* be2 = (const float*)d_in[13];
    const float* g3 = (const float*)d_in[14]; const float* be3 = (const float*)d_in[15];

    float *p_h, *p_t1, *p_t2, *p_t3, *p_out, *p_s1, *p_s2, *p_s3;
    cudaGetSymbolAddress((void**)&p_h,   g_h);
    cudaGetSymbolAddress((void**)&p_t1,  g_t1);
    cudaGetSymbolAddress((void**)&p_t2,  g_t2);
    cudaGetSymbolAddress((void**)&p_t3,  g_t3);
    cudaGetSymbolAddress((void**)&p_out, g_out);
    cudaGetSymbolAddress((void**)&p_s1,  g_s1);
    cudaGetSymbolAddress((void**)&p_s2,  g_s2);
    cudaGetSymbolAddress((void**)&p_s3,  g_s3);

    const int TB = 256;
    // graph build
    k_init <<<(Nn + TB - 1) / TB, TB>>>();
    k_count<<<(Ee + TB - 1) / TB, TB>>>(ei);
    k_dinv <<<(Nn + TB - 1) / TB, TB>>>();
    k_scan <<<1, 1024>>>();
    k_fill <<<(Ee + TB - 1) / TB, TB>>>(ei);

    int gP128 = (Nn + 3) / 4;
    int gGemm = (Nn + BM - 1) / BM;
    int gBn   = (Nn * (Hd / 4) + TB - 1) / TB;

    // layer 1 (F=3)
    k_prop3<<<(Nn + TB - 1) / TB, TB>>>(x, nullptr, p_s1);
    k_prop3<<<(Nn + TB - 1) / TB, TB>>>(p_s1, x, p_s2);
    k_prop3<<<(Nn + TB - 1) / TB, TB>>>(p_s2, p_s1, p_s3);
    k_gemm12<<<(Nn + 31) / 32, Hd>>>(x, p_s1, p_s2, p_s3, W1, b1, p_out);
    k_stats<<<STB, Hd>>>(p_out);
    k_bnfin<<<1, Hd>>>(g1, be1);
    k_bnapply<<<gBn, TB>>>(p_out, p_h);

    // layer 2
    k_prop128<<<gP128, 128>>>(p_h, nullptr, p_t1);
    k_prop128<<<gP128, 128>>>(p_t1, p_h, p_t2);
    k_prop128<<<gP128, 128>>>(p_t2, p_t1, p_t3);
    k_gemm512<<<gGemm, 256>>>(p_h, p_t1, p_t2, p_t3, W2, b2, p_out, 1);
    k_stats<<<STB, Hd>>>(p_out);
    k_bnfin<<<1, Hd>>>(g2, be2);
    k_bnapply<<<gBn, TB>>>(p_out, p_h);

    // layer 3
    k_prop128<<<gP128, 128>>>(p_h, nullptr, p_t1);
    k_prop128<<<gP128, 128>>>(p_t1, p_h, p_t2);
    k_prop128<<<gP128, 128>>>(p_t2, p_t1, p_t3);
    k_gemm512<<<gGemm, 256>>>(p_h, p_t1, p_t2, p_t3, W3, b3, p_out, 2);
    k_stats<<<STB, Hd>>>(p_out);
    k_bnfin<<<1, Hd>>>(g3, be3);
    k_bnapply<<<gBn, TB>>>(p_out, p_h);

    // layer 4 + normalize
    k_prop128<<<gP128, 128>>>(p_h, nullptr, p_t1);
    k_prop128<<<gP128, 128>>>(p_t1, p_h, p_t2);
    k_prop128<<<gP128, 128>>>(p_t2, p_t1, p_t3);
    k_gemm512<<<gGemm, 256>>>(p_h, p_t1, p_t2, p_t3, W4, b4, p_out, 0);
    k_norm<<<Nn, Hd>>>(p_out, (float*)d_out);
}

// round 4
// speedup vs baseline: 1.4530x; 1.4530x over previous
#include <cuda_runtime.h>
#include <cuda_bf16.h>
#include <cstdint>

#define Nn 50000
#define Ee 800000
#define Hd 128
#define STB 200      // stats blocks
#define RPS 250      // rows per stats block (STB*RPS == Nn)
#define SCB 49       // scan blocks (ceil(Nn/1024))

// ---------------- scratch ----------------
__device__ int   g_deg[Nn];
__device__ int   g_cnt[Nn];
__device__ int   g_rowptr[Nn + 1];
__device__ int   g_tmpptr[Nn];
__device__ float g_dinv[Nn];
__device__ int2  g_epk[Ee];          // (src, weight-bits)
__device__ int   g_bsum[SCB];
__device__ int   g_boff[SCB];

__device__ __align__(256) float g_h[Nn * Hd];
__device__ __align__(256) float g_t1[Nn * Hd];
__device__ __align__(256) float g_t2[Nn * Hd];
__device__ __align__(256) float g_t3[Nn * Hd];
__device__ __align__(256) float g_out[Nn * Hd];

__device__ float g_s1[Nn * 3];
__device__ float g_s2[Nn * 3];
__device__ float g_s3[Nn * 3];

__device__ float g_part [STB * Hd];
__device__ float g_part2[STB * Hd];
__device__ float g_scale[Hd];
__device__ float g_shift[Hd];

// ---------------- helpers ----------------
__device__ __forceinline__ uint32_t f2tf32(float f) {
    uint32_t u;
    asm("cvt.rna.tf32.f32 %0, %1;" : "=r"(u) : "f"(f));
    return u;
}
__device__ __forceinline__ void mma_tf32(float* c, const uint32_t* a, const uint32_t* b) {
    asm volatile(
        "mma.sync.aligned.m16n8k8.row.col.f32.tf32.tf32.f32 "
        "{%0,%1,%2,%3}, {%4,%5,%6,%7}, {%8,%9}, {%0,%1,%2,%3};"
        : "+f"(c[0]), "+f"(c[1]), "+f"(c[2]), "+f"(c[3])
        : "r"(a[0]), "r"(a[1]), "r"(a[2]), "r"(a[3]), "r"(b[0]), "r"(b[1]));
}

// ---------------- graph build ----------------
__global__ void k_init() {
    int i = blockIdx.x * blockDim.x + threadIdx.x;
    if (i < Nn) { g_deg[i] = 0; g_cnt[i] = 0; }
}

__global__ void k_count(const int* __restrict__ ei) {
    int e = blockIdx.x * blockDim.x + threadIdx.x;
    if (e < Ee) {
        int s = ei[e];
        int d = ei[e + Ee];
        if ((unsigned)s < Nn) atomicAdd(&g_deg[s], 1);
        if ((unsigned)d < Nn) atomicAdd(&g_cnt[d], 1);
    }
}

__global__ void k_dinv() {
    int i = blockIdx.x * blockDim.x + threadIdx.x;
    if (i < Nn) {
        int d = g_deg[i];
        g_dinv[i] = (d > 0) ? rsqrtf((float)d) : 0.0f;
    }
}

// multi-block scan
__global__ void k_scan1() {
    __shared__ int sd[1024];
    int b = blockIdx.x, tid = threadIdx.x;
    int i = b * 1024 + tid;
    int v = (i < Nn) ? g_cnt[i] : 0;
    sd[tid] = v;
    __syncthreads();
    for (int off = 1; off < 1024; off <<= 1) {
        int t = (tid >= off) ? sd[tid - off] : 0;
        __syncthreads();
        sd[tid] += t;
        __syncthreads();
    }
    if (i < Nn) g_rowptr[i + 1] = sd[tid];
    if (tid == 1023) g_bsum[b] = sd[1023];
}
__global__ void k_scan2() {
    if (threadIdx.x == 0) {
        int acc = 0;
        for (int b = 0; b < SCB; b++) { g_boff[b] = acc; acc += g_bsum[b]; }
        g_rowptr[0] = 0;
    }
}
__global__ void k_scan3() {
    int i = blockIdx.x * blockDim.x + threadIdx.x;
    if (i < Nn) {
        int r = g_rowptr[i + 1] + g_boff[i >> 10];
        g_rowptr[i + 1] = r;
        g_tmpptr[i] = r - g_cnt[i];
    }
}

__global__ void k_fill(const int* __restrict__ ei) {
    int e = blockIdx.x * blockDim.x + threadIdx.x;
    if (e < Ee) {
        int s = ei[e];
        int d = ei[e + Ee];
        if ((unsigned)s >= Nn || (unsigned)d >= Nn) return;
        int p = atomicAdd(&g_tmpptr[d], 1);
        float w = -g_dinv[s] * g_dinv[d];
        g_epk[p] = make_int2(s, __float_as_int(w));
    }
}

// ---------------- propagation ----------------
__global__ void k_prop3(const float* __restrict__ hin,
                        const float* __restrict__ sub,
                        float* __restrict__ out) {
    int v = blockIdx.x * blockDim.x + threadIdx.x;
    if (v >= Nn) return;
    float a0 = 0.f, a1 = 0.f, a2 = 0.f;
    int b = g_rowptr[v], en = g_rowptr[v + 1];
    for (int i = b; i < en; i++) {
        int2 e = g_epk[i];
        float w = __int_as_float(e.y);
        const float* hp = hin + e.x * 3;
        a0 += w * hp[0]; a1 += w * hp[1]; a2 += w * hp[2];
    }
    float* o = out + v * 3;
    if (sub) {
        const float* sv = sub + v * 3;
        o[0] = 2.f * a0 - sv[0]; o[1] = 2.f * a1 - sv[1]; o[2] = 2.f * a2 - sv[2];
    } else {
        o[0] = a0; o[1] = a1; o[2] = a2;
    }
}

// warp per node, float4 per lane, 4 warps per block
__global__ void k_prop128(const float* __restrict__ hin,
                          const float* __restrict__ sub,
                          float* __restrict__ out) {
    int v = blockIdx.x * 4 + (threadIdx.x >> 5);
    if (v >= Nn) return;
    int lane = threadIdx.x & 31;
    int b = g_rowptr[v], en = g_rowptr[v + 1];
    float4 acc = make_float4(0.f, 0.f, 0.f, 0.f);
    int i = b;
    for (; i + 1 < en; i += 2) {
        int2 e0 = g_epk[i];
        int2 e1 = g_epk[i + 1];
        float w0 = __int_as_float(e0.y);
        float w1 = __int_as_float(e1.y);
        float4 v0 = *(const float4*)(hin + e0.x * Hd + lane * 4);
        float4 v1 = *(const float4*)(hin + e1.x * Hd + lane * 4);
        acc.x += w0 * v0.x + w1 * v1.x;
        acc.y += w0 * v0.y + w1 * v1.y;
        acc.z += w0 * v0.z + w1 * v1.z;
        acc.w += w0 * v0.w + w1 * v1.w;
    }
    if (i < en) {
        int2 e = g_epk[i];
        float w = __int_as_float(e.y);
        float4 g = *(const float4*)(hin + e.x * Hd + lane * 4);
        acc.x += w * g.x; acc.y += w * g.y; acc.z += w * g.z; acc.w += w * g.w;
    }
    float4 r;
    if (sub) {
        float4 sv = *(const float4*)(sub + v * Hd + lane * 4);
        r.x = 2.f * acc.x - sv.x; r.y = 2.f * acc.y - sv.y;
        r.z = 2.f * acc.z - sv.z; r.w = 2.f * acc.w - sv.w;
    } else {
        r = acc;
    }
    *(float4*)(out + v * Hd + lane * 4) = r;
}

// ---------------- layer 1 GEMM: K=12 ----------------
__global__ void k_gemm12(const float* __restrict__ x,  const float* __restrict__ t1,
                         const float* __restrict__ t2, const float* __restrict__ t3,
                         const float* __restrict__ W,  const float* __restrict__ bias,
                         float* __restrict__ out) {
    __shared__ float sW[12 * Hd];
    int c = threadIdx.x;
    #pragma unroll
    for (int j = 0; j < 12; j++) sW[j * Hd + c] = W[j * Hd + c];
    __syncthreads();
    const int RPB = 32;
    int v0 = blockIdx.x * RPB;
    float bv = bias[c];
    for (int r = 0; r < RPB; r++) {
        int v = v0 + r;
        if (v >= Nn) break;
        float a[12];
        #pragma unroll
        for (int f = 0; f < 3; f++) {
            a[f]     = x [v * 3 + f];
            a[3 + f] = t1[v * 3 + f];
            a[6 + f] = t2[v * 3 + f];
            a[9 + f] = t3[v * 3 + f];
        }
        float acc = bv;
        #pragma unroll
        for (int j = 0; j < 12; j++) acc += a[j] * sW[j * Hd + c];
        acc = (acc > 0.f) ? acc : 0.01f * acc;   // leaky relu
        out[v * Hd + c] = acc;
    }
}

// ---------------- tensor-core GEMM (mma.sync tf32): M=Nn, K=512, N=128 ----
// A = [Tx0|Tx1|Tx2|Tx3] (each [Nn,128] row-major), B = W [512][128] row-major.
#define BM 128
#define BN 128
#define BK 16
#define ASTR (BK + 4)     // 20, A smem m-major stride
#define BSTR (BN + 4)     // 132, B smem k-major stride

__global__ __launch_bounds__(256)
void k_gemm_mma(const float* __restrict__ A0, const float* __restrict__ A1,
                const float* __restrict__ A2, const float* __restrict__ A3,
                const float* __restrict__ W,  const float* __restrict__ bias,
                float* __restrict__ out, int act) {
    __shared__ uint32_t As[BM][ASTR];   // tf32 bits, m-major
    __shared__ uint32_t Bs[BK][BSTR];   // tf32 bits, k-major
    const float* Abuf[4] = {A0, A1, A2, A3};

    int tid = threadIdx.x;
    int wid = tid >> 5;
    int lane = tid & 31;
    int grp = lane >> 2;       // 0..7
    int tig = lane & 3;        // 0..3
    int m_base = (wid >> 1) * 32;
    int n_base = (wid & 1) * 64;
    int row0 = blockIdx.x * BM;

    float c[2][8][4];
    #pragma unroll
    for (int mi = 0; mi < 2; mi++)
        #pragma unroll
        for (int ni = 0; ni < 8; ni++)
            #pragma unroll
            for (int q = 0; q < 4; q++) c[mi][ni][q] = 0.f;

    // loader indices
    int la_r  = tid >> 1;             // 0..127  (A: 2 float4 per row of 16)
    int la_c4 = (tid & 1) * 8;        // 0 or 8
    int lb_k  = tid >> 5;             // 0..7    (B: 8 k-rows per pass, 2 passes)
    int lb_c4 = (tid & 31) * 4;       // 0..124

    for (int kt = 0; kt < 32; kt++) {
        const float* A = Abuf[kt >> 3];
        int cb = (kt & 7) * BK;
        // A tile: 128 rows x 16 k  (each thread: 2 float4)
        {
            int gr = row0 + la_r;
            float4 v0 = make_float4(0.f,0.f,0.f,0.f), v1 = v0;
            if (gr < Nn) {
                const float4* src = (const float4*)(A + gr * Hd + cb + la_c4);
                v0 = src[0]; v1 = src[1];
            }
            uint4 u0 = make_uint4(f2tf32(v0.x), f2tf32(v0.y), f2tf32(v0.z), f2tf32(v0.w));
            uint4 u1 = make_uint4(f2tf32(v1.x), f2tf32(v1.y), f2tf32(v1.z), f2tf32(v1.w));
            *(uint4*)&As[la_r][la_c4]     = u0;
            *(uint4*)&As[la_r][la_c4 + 4] = u1;
        }
        // B tile: 16 k-rows x 128 n (each thread: 2 float4, k and k+8)
        {
            #pragma unroll
            for (int p = 0; p < 2; p++) {
                int kk = lb_k + p * 8;
                const float4* src = (const float4*)(W + (kt * BK + kk) * Hd + lb_c4);
                float4 v = src[0];
                uint4 u = make_uint4(f2tf32(v.x), f2tf32(v.y), f2tf32(v.z), f2tf32(v.w));
                *(uint4*)&Bs[kk][lb_c4] = u;
            }
        }
        __syncthreads();
        #pragma unroll
        for (int ks = 0; ks < 2; ks++) {
            int kk0 = ks * 8;
            uint32_t a[2][4], b[8][2];
            #pragma unroll
            for (int mi = 0; mi < 2; mi++) {
                int m0 = m_base + mi * 16 + grp;
                a[mi][0] = As[m0][kk0 + tig];
                a[mi][1] = As[m0 + 8][kk0 + tig];
                a[mi][2] = As[m0][kk0 + tig + 4];
                a[mi][3] = As[m0 + 8][kk0 + tig + 4];
            }
            #pragma unroll
            for (int ni = 0; ni < 8; ni++) {
                int nc = n_base + ni * 8 + grp;
                b[ni][0] = Bs[kk0 + tig][nc];
                b[ni][1] = Bs[kk0 + tig + 4][nc];
            }
            #pragma unroll
            for (int mi = 0; mi < 2; mi++)
                #pragma unroll
                for (int ni = 0; ni < 8; ni++)
                    mma_tf32(c[mi][ni], a[mi], b[ni]);
        }
        __syncthreads();
    }

    // epilogue
    #pragma unroll
    for (int mi = 0; mi < 2; mi++) {
        #pragma unroll
        for (int half = 0; half < 2; half++) {
            int row = row0 + m_base + mi * 16 + grp + half * 8;
            if (row < Nn) {
                #pragma unroll
                for (int ni = 0; ni < 8; ni++) {
                    int col = n_base + ni * 8 + tig * 2;
                    float f0 = c[mi][ni][half * 2 + 0] + __ldg(bias + col);
                    float f1 = c[mi][ni][half * 2 + 1] + __ldg(bias + col + 1);
                    if (act == 1) {
                        f0 = (f0 > 0.f) ? f0 : 0.01f * f0;
                        f1 = (f1 > 0.f) ? f1 : 0.01f * f1;
                    } else if (act == 2) {
                        f0 = fmaxf(f0, 0.f); f1 = fmaxf(f1, 0.f);
                    }
                    *(float2*)(out + row * Hd + col) = make_float2(f0, f1);
                }
            }
        }
    }
}

// ---------------- BN (deterministic two-stage) ----------------
__global__ void k_stats(const float* __restrict__ h) {
    int c = threadIdx.x;
    int b = blockIdx.x;
    float s = 0.f, s2 = 0.f;
    int v0 = b * RPS;
    for (int r = 0; r < RPS; r++) {
        float x = h[(v0 + r) * Hd + c];
        s += x; s2 += x * x;
    }
    g_part [b * Hd + c] = s;
    g_part2[b * Hd + c] = s2;
}

__global__ void k_bnfin(const float* __restrict__ gamma, const float* __restrict__ beta) {
    int c = threadIdx.x;
    float s = 0.f, s2 = 0.f;
    for (int b = 0; b < STB; b++) { s += g_part[b * Hd + c]; s2 += g_part2[b * Hd + c]; }
    float m   = s / (float)Nn;
    float var = s2 / (float)Nn - m * m;
    float inv = rsqrtf(var + 1e-5f);
    float sc  = gamma[c] * inv;
    g_scale[c] = sc;
    g_shift[c] = beta[c] - m * sc;
}

__global__ void k_bnapply(const float* __restrict__ in, float* __restrict__ outp) {
    int i = blockIdx.x * blockDim.x + threadIdx.x;
    if (i < Nn * (Hd / 4)) {
        float4 v = ((const float4*)in)[i];
        int c = (i & (Hd / 4 - 1)) * 4;
        v.x = v.x * g_scale[c + 0] + g_shift[c + 0];
        v.y = v.y * g_scale[c + 1] + g_shift[c + 1];
        v.z = v.z * g_scale[c + 2] + g_shift[c + 2];
        v.w = v.w * g_scale[c + 3] + g_shift[c + 3];
        ((float4*)outp)[i] = v;
    }
}

// ---------------- final L2 row-normalize ----------------
__global__ void k_norm(const float* __restrict__ in, float* __restrict__ outp) {
    int v = blockIdx.x;
    int c = threadIdx.x;
    float x = in[v * Hd + c];
    float s = x * x;
    __shared__ float ws[4];
    #pragma unroll
    for (int o = 16; o; o >>= 1) s += __shfl_xor_sync(0xffffffffu, s, o);
    if ((c & 31) == 0) ws[c >> 5] = s;
    __syncthreads();
    float tot = ws[0] + ws[1] + ws[2] + ws[3];
    float nrm = fmaxf(sqrtf(tot), 1e-12f);
    outp[v * Hd + c] = x / nrm;
}

// ---------------- host ----------------
extern "C" void kernel_launch(void* const* d_in, const int* in_sizes, int n_in,
                              void* d_out, int out_size) {
    const float* x  = (const float*)d_in[0];
    const int*   ei = (const int*)d_in[1];   // int32 (JAX x64 disabled)
    const float* W1 = (const float*)d_in[2];  const float* b1 = (const float*)d_in[3];
    const float* W2 = (const float*)d_in[4];  const float* b2 = (const float*)d_in[5];
    const float* W3 = (const float*)d_in[6];  const float* b3 = (const float*)d_in[7];
    const float* W4 = (const float*)d_in[8];  const float* b4 = (const float*)d_in[9];
    const float* g1 = (const float*)d_in[10]; const float* be1 = (const float*)d_in[11];
    const float* g2 = (const float*)d_in[12]; const float* be2 = (const float*)d_in[13];
    const float* g3 = (const float*)d_in[14]; const float* be3 = (const float*)d_in[15];

    float *p_h, *p_t1, *p_t2, *p_t3, *p_out, *p_s1, *p_s2, *p_s3;
    cudaGetSymbolAddress((void**)&p_h,   g_h);
    cudaGetSymbolAddress((void**)&p_t1,  g_t1);
    cudaGetSymbolAddress((void**)&p_t2,  g_t2);
    cudaGetSymbolAddress((void**)&p_t3,  g_t3);
    cudaGetSymbolAddress((void**)&p_out, g_out);
    cudaGetSymbolAddress((void**)&p_s1,  g_s1);
    cudaGetSymbolAddress((void**)&p_s2,  g_s2);
    cudaGetSymbolAddress((void**)&p_s3,  g_s3);

    const int TB = 256;
    // graph build
    k_init <<<(Nn + TB - 1) / TB, TB>>>();
    k_count<<<(Ee + TB - 1) / TB, TB>>>(ei);
    k_dinv <<<(Nn + TB - 1) / TB, TB>>>();
    k_scan1<<<SCB, 1024>>>();
    k_scan2<<<1, 64>>>();
    k_scan3<<<(Nn + TB - 1) / TB, TB>>>();
    k_fill <<<(Ee + TB - 1) / TB, TB>>>(ei);

    int gP128 = (Nn + 3) / 4;
    int gGemm = (Nn + BM - 1) / BM;
    int gBn   = (Nn * (Hd / 4) + TB - 1) / TB;

    // layer 1 (F=3)
    k_prop3<<<(Nn + TB - 1) / TB, TB>>>(x, nullptr, p_s1);
    k_prop3<<<(Nn + TB - 1) / TB, TB>>>(p_s1, x, p_s2);
    k_prop3<<<(Nn + TB - 1) / TB, TB>>>(p_s2, p_s1, p_s3);
    k_gemm12<<<(Nn + 31) / 32, Hd>>>(x, p_s1, p_s2, p_s3, W1, b1, p_out);
    k_stats<<<STB, Hd>>>(p_out);
    k_bnfin<<<1, Hd>>>(g1, be1);
    k_bnapply<<<gBn, TB>>>(p_out, p_h);

    // layer 2
    k_prop128<<<gP128, 128>>>(p_h, nullptr, p_t1);
    k_prop128<<<gP128, 128>>>(p_t1, p_h, p_t2);
    k_prop128<<<gP128, 128>>>(p_t2, p_t1, p_t3);
    k_gemm_mma<<<gGemm, 256>>>(p_h, p_t1, p_t2, p_t3, W2, b2, p_out, 1);
    k_stats<<<STB, Hd>>>(p_out);
    k_bnfin<<<1, Hd>>>(g2, be2);
    k_bnapply<<<gBn, TB>>>(p_out, p_h);

    // layer 3
    k_prop128<<<gP128, 128>>>(p_h, nullptr, p_t1);
    k_prop128<<<gP128, 128>>>(p_t1, p_h, p_t2);
    k_prop128<<<gP128, 128>>>(p_t2, p_t1, p_t3);
    k_gemm_mma<<<gGemm, 256>>>(p_h, p_t1, p_t2, p_t3, W3, b3, p_out, 2);
    k_stats<<<STB, Hd>>>(p_out);
    k_bnfin<<<1, Hd>>>(g3, be3);
    k_bnapply<<<gBn, TB>>>(p_out, p_h);

    // layer 4 + normalize
    k_prop128<<<gP128, 128>>>(p_h, nullptr, p_t1);
    k_prop128<<<gP128, 128>>>(p_t1, p_h, p_t2);
    k_prop128<<<gP128, 128>>>(p_t2, p_t1, p_t3);
    k_gemm_mma<<<gGemm, 256>>>(p_h, p_t1, p_t2, p_t3, W4, b4, p_out, 0);
    k_norm<<<Nn, Hd>>>(p_out, (float*)d_out);
}

// round 5
// speedup vs baseline: 1.5078x; 1.0377x over previous
#include <cuda_runtime.h>
#include <cuda_bf16.h>
#include <cstdint>

#define Nn 50000
#define Ee 800000
#define Hd 128
#define SCB 49       // scan blocks (ceil(Nn/1024))
#define PMAX 1600    // max stats-partial blocks (gemm12 uses 1563)

// ---------------- scratch ----------------
__device__ int   g_deg[Nn];
__device__ int   g_cnt[Nn];
__device__ int   g_rowptr[Nn + 1];
__device__ int   g_tmpptr[Nn];
__device__ float g_dinv[Nn];
__device__ int2  g_epk[Ee];          // (src, weight-bits)
__device__ int   g_bsum[SCB];
__device__ int   g_boff[SCB];

__device__ __align__(256) float g_t1[Nn * Hd];
__device__ __align__(256) float g_t2[Nn * Hd];
__device__ __align__(256) float g_t3[Nn * Hd];
__device__ __align__(256) float g_out[Nn * Hd];

__device__ float g_s1[Nn * 3];
__device__ float g_s2[Nn * 3];
__device__ float g_s3[Nn * 3];

__device__ float g_part [PMAX * Hd];
__device__ float g_part2[PMAX * Hd];
__device__ float g_scale[Hd];
__device__ float g_shift[Hd];

// ---------------- helpers ----------------
__device__ __forceinline__ uint32_t f2tf32(float f) {
    uint32_t u;
    asm("cvt.rna.tf32.f32 %0, %1;" : "=r"(u) : "f"(f));
    return u;
}
__device__ __forceinline__ void mma_tf32(float* c, const uint32_t* a, const uint32_t* b) {
    asm volatile(
        "mma.sync.aligned.m16n8k8.row.col.f32.tf32.tf32.f32 "
        "{%0,%1,%2,%3}, {%4,%5,%6,%7}, {%8,%9}, {%0,%1,%2,%3};"
        : "+f"(c[0]), "+f"(c[1]), "+f"(c[2]), "+f"(c[3])
        : "r"(a[0]), "r"(a[1]), "r"(a[2]), "r"(a[3]), "r"(b[0]), "r"(b[1]));
}

// ---------------- graph build ----------------
__global__ void k_init() {
    int i = blockIdx.x * blockDim.x + threadIdx.x;
    if (i < Nn) { g_deg[i] = 0; g_cnt[i] = 0; }
}

__global__ void k_count(const int* __restrict__ ei) {
    int e = blockIdx.x * blockDim.x + threadIdx.x;
    if (e < Ee) {
        int s = ei[e];
        int d = ei[e + Ee];
        if ((unsigned)s < Nn) atomicAdd(&g_deg[s], 1);
        if ((unsigned)d < Nn) atomicAdd(&g_cnt[d], 1);
    }
}

__global__ void k_dinv() {
    int i = blockIdx.x * blockDim.x + threadIdx.x;
    if (i < Nn) {
        int d = g_deg[i];
        g_dinv[i] = (d > 0) ? rsqrtf((float)d) : 0.0f;
    }
}

__global__ void k_scan1() {
    __shared__ int sd[1024];
    int b = blockIdx.x, tid = threadIdx.x;
    int i = b * 1024 + tid;
    int v = (i < Nn) ? g_cnt[i] : 0;
    sd[tid] = v;
    __syncthreads();
    for (int off = 1; off < 1024; off <<= 1) {
        int t = (tid >= off) ? sd[tid - off] : 0;
        __syncthreads();
        sd[tid] += t;
        __syncthreads();
    }
    if (i < Nn) g_rowptr[i + 1] = sd[tid];
    if (tid == 1023) g_bsum[b] = sd[1023];
}
__global__ void k_scan2() {
    if (threadIdx.x == 0) {
        int acc = 0;
        for (int b = 0; b < SCB; b++) { g_boff[b] = acc; acc += g_bsum[b]; }
        g_rowptr[0] = 0;
    }
}
__global__ void k_scan3() {
    int i = blockIdx.x * blockDim.x + threadIdx.x;
    if (i < Nn) {
        int r = g_rowptr[i + 1] + g_boff[i >> 10];
        g_rowptr[i + 1] = r;
        g_tmpptr[i] = r - g_cnt[i];
    }
}

__global__ void k_fill(const int* __restrict__ ei) {
    int e = blockIdx.x * blockDim.x + threadIdx.x;
    if (e < Ee) {
        int s = ei[e];
        int d = ei[e + Ee];
        if ((unsigned)s >= Nn || (unsigned)d >= Nn) return;
        int p = atomicAdd(&g_tmpptr[d], 1);
        float w = -g_dinv[s] * g_dinv[d];
        g_epk[p] = make_int2(s, __float_as_int(w));
    }
}

// ---------------- propagation ----------------
__global__ void k_prop3(const float* __restrict__ hin,
                        const float* __restrict__ sub,
                        float* __restrict__ out) {
    int v = blockIdx.x * blockDim.x + threadIdx.x;
    if (v >= Nn) return;
    float a0 = 0.f, a1 = 0.f, a2 = 0.f;
    int b = g_rowptr[v], en = g_rowptr[v + 1];
    for (int i = b; i < en; i++) {
        int2 e = g_epk[i];
        float w = __int_as_float(e.y);
        const float* hp = hin + e.x * 3;
        a0 += w * hp[0]; a1 += w * hp[1]; a2 += w * hp[2];
    }
    float* o = out + v * 3;
    if (sub) {
        const float* sv = sub + v * 3;
        o[0] = 2.f * a0 - sv[0]; o[1] = 2.f * a1 - sv[1]; o[2] = 2.f * a2 - sv[2];
    } else {
        o[0] = a0; o[1] = a1; o[2] = a2;
    }
}

// warp per node. mode: 0 = plain (optional sub), 1 = BN on hin (no sub),
// 2 = BN on sub (hin plain).
__global__ void k_prop128(const float* __restrict__ hin,
                          const float* __restrict__ sub,
                          float* __restrict__ out,
                          const float* __restrict__ sc,
                          const float* __restrict__ sh,
                          int mode) {
    int v = blockIdx.x * 4 + (threadIdx.x >> 5);
    if (v >= Nn) return;
    int lane = threadIdx.x & 31;
    float4 sc4, sh4;
    if (mode) {
        sc4 = ((const float4*)sc)[lane];
        sh4 = ((const float4*)sh)[lane];
    }
    int b = g_rowptr[v], en = g_rowptr[v + 1];
    float4 acc = make_float4(0.f, 0.f, 0.f, 0.f);
    float wsum = 0.f;
    int i = b;
    for (; i + 1 < en; i += 2) {
        int2 e0 = g_epk[i];
        int2 e1 = g_epk[i + 1];
        float w0 = __int_as_float(e0.y);
        float w1 = __int_as_float(e1.y);
        float4 v0 = *(const float4*)(hin + e0.x * Hd + lane * 4);
        float4 v1 = *(const float4*)(hin + e1.x * Hd + lane * 4);
        acc.x += w0 * v0.x + w1 * v1.x;
        acc.y += w0 * v0.y + w1 * v1.y;
        acc.z += w0 * v0.z + w1 * v1.z;
        acc.w += w0 * v0.w + w1 * v1.w;
        wsum += w0 + w1;
    }
    if (i < en) {
        int2 e = g_epk[i];
        float w = __int_as_float(e.y);
        float4 g = *(const float4*)(hin + e.x * Hd + lane * 4);
        acc.x += w * g.x; acc.y += w * g.y; acc.z += w * g.z; acc.w += w * g.w;
        wsum += w;
    }
    float4 r;
    if (mode == 1) {
        // prop(sc*h+sh) = sc*prop(h) + sh*sum(w)
        r.x = sc4.x * acc.x + sh4.x * wsum;
        r.y = sc4.y * acc.y + sh4.y * wsum;
        r.z = sc4.z * acc.z + sh4.z * wsum;
        r.w = sc4.w * acc.w + sh4.w * wsum;
    } else if (mode == 2) {
        float4 sv = *(const float4*)(sub + v * Hd + lane * 4);
        r.x = 2.f * acc.x - (sc4.x * sv.x + sh4.x);
        r.y = 2.f * acc.y - (sc4.y * sv.y + sh4.y);
        r.z = 2.f * acc.z - (sc4.z * sv.z + sh4.z);
        r.w = 2.f * acc.w - (sc4.w * sv.w + sh4.w);
    } else if (sub) {
        float4 sv = *(const float4*)(sub + v * Hd + lane * 4);
        r.x = 2.f * acc.x - sv.x; r.y = 2.f * acc.y - sv.y;
        r.z = 2.f * acc.z - sv.z; r.w = 2.f * acc.w - sv.w;
    } else {
        r = acc;
    }
    *(float4*)(out + v * Hd + lane * 4) = r;
}

// ---------------- layer 1 GEMM: K=12 (+ fused stats partials) ----------------
__global__ void k_gemm12(const float* __restrict__ x,  const float* __restrict__ t1,
                         const float* __restrict__ t2, const float* __restrict__ t3,
                         const float* __restrict__ W,  const float* __restrict__ bias,
                         float* __restrict__ out) {
    __shared__ float sW[12 * Hd];
    int c = threadIdx.x;
    #pragma unroll
    for (int j = 0; j < 12; j++) sW[j * Hd + c] = W[j * Hd + c];
    __syncthreads();
    const int RPB = 32;
    int v0 = blockIdx.x * RPB;
    float bv = bias[c];
    float s = 0.f, s2 = 0.f;
    for (int r = 0; r < RPB; r++) {
        int v = v0 + r;
        if (v >= Nn) break;
        float a[12];
        #pragma unroll
        for (int f = 0; f < 3; f++) {
            a[f]     = x [v * 3 + f];
            a[3 + f] = t1[v * 3 + f];
            a[6 + f] = t2[v * 3 + f];
            a[9 + f] = t3[v * 3 + f];
        }
        float acc = bv;
        #pragma unroll
        for (int j = 0; j < 12; j++) acc += a[j] * sW[j * Hd + c];
        acc = (acc > 0.f) ? acc : 0.01f * acc;   // leaky relu
        out[v * Hd + c] = acc;
        s += acc; s2 += acc * acc;
    }
    g_part [blockIdx.x * Hd + c] = s;
    g_part2[blockIdx.x * Hd + c] = s2;
}

// ---------------- tensor-core GEMM (mma.sync tf32) + fused epilogues --------
// mode: 1 = leaky+stats, 2 = relu+stats, 0 = no-act + row-L2-normalize
#define BM 128
#define BK 16
#define ASTR (BK + 4)     // 20
#define BSTR (Hd + 8)     // 136: B frag banks = 8*tig + grp, conflict-free

__global__ __launch_bounds__(256)
void k_gemm_mma(const float* __restrict__ A0, const float* __restrict__ A1,
                const float* __restrict__ A2, const float* __restrict__ A3,
                const float* __restrict__ W,  const float* __restrict__ bias,
                float* __restrict__ out,
                const float* __restrict__ scA, const float* __restrict__ shA,
                int mode) {
    __shared__ uint32_t As[BM][ASTR];
    __shared__ uint32_t Bs[BK][BSTR];
    __shared__ float sred [8][64];
    __shared__ float sred2[8][64];
    __shared__ float rows2[2][BM];
    const float* Abuf[4] = {A0, A1, A2, A3};

    int tid = threadIdx.x;
    int wid = tid >> 5;
    int lane = tid & 31;
    int grp = lane >> 2;       // 0..7
    int tig = lane & 3;        // 0..3
    int m_base = (wid >> 1) * 32;
    int n_base = (wid & 1) * 64;
    int row0 = blockIdx.x * BM;

    float c[2][8][4];
    #pragma unroll
    for (int mi = 0; mi < 2; mi++)
        #pragma unroll
        for (int ni = 0; ni < 8; ni++)
            #pragma unroll
            for (int q = 0; q < 4; q++) c[mi][ni][q] = 0.f;

    int la_r  = tid >> 1;
    int la_c4 = (tid & 1) * 8;
    int lb_k  = tid >> 5;
    int lb_c4 = (tid & 31) * 4;

    for (int kt = 0; kt < 32; kt++) {
        const float* A = Abuf[kt >> 3];
        int cb = (kt & 7) * BK;
        {
            int gr = row0 + la_r;
            float4 v0 = make_float4(0.f,0.f,0.f,0.f), v1 = v0;
            if (gr < Nn) {
                const float4* src = (const float4*)(A + gr * Hd + cb + la_c4);
                v0 = src[0]; v1 = src[1];
            }
            if (scA && (kt >> 3) == 0) {   // A0 = BN(h): apply scale/shift inline
                float4 s0 = *(const float4*)(scA + cb + la_c4);
                float4 s1 = *(const float4*)(scA + cb + la_c4 + 4);
                float4 h0 = *(const float4*)(shA + cb + la_c4);
                float4 h1 = *(const float4*)(shA + cb + la_c4 + 4);
                v0.x = v0.x * s0.x + h0.x; v0.y = v0.y * s0.y + h0.y;
                v0.z = v0.z * s0.z + h0.z; v0.w = v0.w * s0.w + h0.w;
                v1.x = v1.x * s1.x + h1.x; v1.y = v1.y * s1.y + h1.y;
                v1.z = v1.z * s1.z + h1.z; v1.w = v1.w * s1.w + h1.w;
                if (row0 + la_r >= Nn) { v0 = make_float4(0,0,0,0); v1 = v0; }
            }
            uint4 u0 = make_uint4(f2tf32(v0.x), f2tf32(v0.y), f2tf32(v0.z), f2tf32(v0.w));
            uint4 u1 = make_uint4(f2tf32(v1.x), f2tf32(v1.y), f2tf32(v1.z), f2tf32(v1.w));
            *(uint4*)&As[la_r][la_c4]     = u0;
            *(uint4*)&As[la_r][la_c4 + 4] = u1;
        }
        {
            #pragma unroll
            for (int p = 0; p < 2; p++) {
                int kk = lb_k + p * 8;
                float4 v = *(const float4*)(W + (kt * BK + kk) * Hd + lb_c4);
                uint4 u = make_uint4(f2tf32(v.x), f2tf32(v.y), f2tf32(v.z), f2tf32(v.w));
                *(uint4*)&Bs[kk][lb_c4] = u;
            }
        }
        __syncthreads();
        #pragma unroll
        for (int ks = 0; ks < 2; ks++) {
            int kk0 = ks * 8;
            uint32_t a[2][4], b[8][2];
            #pragma unroll
            for (int mi = 0; mi < 2; mi++) {
                int m0 = m_base + mi * 16 + grp;
                a[mi][0] = As[m0][kk0 + tig];
                a[mi][1] = As[m0 + 8][kk0 + tig];
                a[mi][2] = As[m0][kk0 + tig + 4];
                a[mi][3] = As[m0 + 8][kk0 + tig + 4];
            }
            #pragma unroll
            for (int ni = 0; ni < 8; ni++) {
                int nc = n_base + ni * 8 + grp;
                b[ni][0] = Bs[kk0 + tig][nc];
                b[ni][1] = Bs[kk0 + tig + 4][nc];
            }
            #pragma unroll
            for (int mi = 0; mi < 2; mi++)
                #pragma unroll
                for (int ni = 0; ni < 8; ni++)
                    mma_tf32(c[mi][ni], a[mi], b[ni]);
        }
        __syncthreads();
    }

    // ---- bias + activation (zero invalid rows) ----
    #pragma unroll
    for (int mi = 0; mi < 2; mi++) {
        #pragma unroll
        for (int half = 0; half < 2; half++) {
            int row = row0 + m_base + mi * 16 + grp + half * 8;
            bool valid = row < Nn;
            #pragma unroll
            for (int ni = 0; ni < 8; ni++) {
                #pragma unroll
                for (int par = 0; par < 2; par++) {
                    int q = half * 2 + par;
                    int col = n_base + ni * 8 + tig * 2 + par;
                    float f = c[mi][ni][q] + __ldg(bias + col);
                    if (mode == 1)      f = (f > 0.f) ? f : 0.01f * f;
                    else if (mode == 2) f = fmaxf(f, 0.f);
                    c[mi][ni][q] = valid ? f : 0.f;
                }
            }
        }
    }

    float rscale[2][2] = {{1.f,1.f},{1.f,1.f}};

    if (mode != 0) {
        // ---- fused BN stats: per-CTA column partials (deterministic) ----
        float ls[8][2], ls2[8][2];
        #pragma unroll
        for (int ni = 0; ni < 8; ni++)
            #pragma unroll
            for (int par = 0; par < 2; par++) {
                float s = 0.f, s2 = 0.f;
                #pragma unroll
                for (int mi = 0; mi < 2; mi++)
                    #pragma unroll
                    for (int half = 0; half < 2; half++) {
                        float f = c[mi][ni][half * 2 + par];
                        s += f; s2 += f * f;
                    }
                ls[ni][par] = s; ls2[ni][par] = s2;
            }
        #pragma unroll
        for (int off = 4; off < 32; off <<= 1) {
            #pragma unroll
            for (int ni = 0; ni < 8; ni++)
                #pragma unroll
                for (int par = 0; par < 2; par++) {
                    ls [ni][par] += __shfl_xor_sync(0xffffffffu, ls [ni][par], off);
                    ls2[ni][par] += __shfl_xor_sync(0xffffffffu, ls2[ni][par], off);
                }
        }
        if (lane < 4) {   // grp == 0
            #pragma unroll
            for (int ni = 0; ni < 8; ni++)
                #pragma unroll
                for (int par = 0; par < 2; par++) {
                    sred [wid][ni * 8 + tig * 2 + par] = ls [ni][par];
                    sred2[wid][ni * 8 + tig * 2 + par] = ls2[ni][par];
                }
        }
        __syncthreads();
        if (tid < Hd) {
            int hf = tid >> 6, cl = tid & 63;
            float s = 0.f, s2 = 0.f;
            #pragma unroll
            for (int j = 0; j < 4; j++) {
                s  += sred [2 * j + hf][cl];
                s2 += sred2[2 * j + hf][cl];
            }
            g_part [blockIdx.x * Hd + tid] = s;
            g_part2[blockIdx.x * Hd + tid] = s2;
        }
    } else {
        // ---- fused row L2 normalize ----
        #pragma unroll
        for (int mi = 0; mi < 2; mi++)
            #pragma unroll
            for (int half = 0; half < 2; half++) {
                float rsq = 0.f;
                #pragma unroll
                for (int ni = 0; ni < 8; ni++) {
                    float f0 = c[mi][ni][half * 2 + 0];
                    float f1 = c[mi][ni][half * 2 + 1];
                    rsq += f0 * f0 + f1 * f1;
                }
                rsq += __shfl_xor_sync(0xffffffffu, rsq, 1);
                rsq += __shfl_xor_sync(0xffffffffu, rsq, 2);
                if (tig == 0)
                    rows2[wid & 1][m_base + mi * 16 + grp + half * 8] = rsq;
            }
        __syncthreads();
        #pragma unroll
        for (int mi = 0; mi < 2; mi++)
            #pragma unroll
            for (int half = 0; half < 2; half++) {
                int rl = m_base + mi * 16 + grp + half * 8;
                float tot = rows2[0][rl] + rows2[1][rl];
                rscale[mi][half] = 1.f / fmaxf(sqrtf(tot), 1e-12f);
            }
    }

    // ---- store ----
    #pragma unroll
    for (int mi = 0; mi < 2; mi++) {
        #pragma unroll
        for (int half = 0; half < 2; half++) {
            int row = row0 + m_base + mi * 16 + grp + half * 8;
            if (row < Nn) {
                float rs = rscale[mi][half];
                #pragma unroll
                for (int ni = 0; ni < 8; ni++) {
                    int col = n_base + ni * 8 + tig * 2;
                    float f0 = c[mi][ni][half * 2 + 0] * rs;
                    float f1 = c[mi][ni][half * 2 + 1] * rs;
                    *(float2*)(out + row * Hd + col) = make_float2(f0, f1);
                }
            }
        }
    }
}

// ---------------- BN finalize ----------------
__global__ void k_bnfin(const float* __restrict__ gamma, const float* __restrict__ beta,
                        int nb) {
    int c = threadIdx.x;
    float s = 0.f, s2 = 0.f;
    for (int b = 0; b < nb; b++) { s += g_part[b * Hd + c]; s2 += g_part2[b * Hd + c]; }
    float m   = s / (float)Nn;
    float var = s2 / (float)Nn - m * m;
    float inv = rsqrtf(var + 1e-5f);
    float sc  = gamma[c] * inv;
    g_scale[c] = sc;
    g_shift[c] = beta[c] - m * sc;
}

// ---------------- host ----------------
extern "C" void kernel_launch(void* const* d_in, const int* in_sizes, int n_in,
                              void* d_out, int out_size) {
    const float* x  = (const float*)d_in[0];
    const int*   ei = (const int*)d_in[1];   // int32 (JAX x64 disabled)
    const float* W1 = (const float*)d_in[2];  const float* b1 = (const float*)d_in[3];
    const float* W2 = (const float*)d_in[4];  const float* b2 = (const float*)d_in[5];
    const float* W3 = (const float*)d_in[6];  const float* b3 = (const float*)d_in[7];
    const float* W4 = (const float*)d_in[8];  const float* b4 = (const float*)d_in[9];
    const float* g1 = (const float*)d_in[10]; const float* be1 = (const float*)d_in[11];
    const float* g2 = (const float*)d_in[12]; const float* be2 = (const float*)d_in[13];
    const float* g3 = (const float*)d_in[14]; const float* be3 = (const float*)d_in[15];

    float *p_t1, *p_t2, *p_t3, *p_out, *p_s1, *p_s2, *p_s3, *p_sc, *p_sh;
    cudaGetSymbolAddress((void**)&p_t1,  g_t1);
    cudaGetSymbolAddress((void**)&p_t2,  g_t2);
    cudaGetSymbolAddress((void**)&p_t3,  g_t3);
    cudaGetSymbolAddress((void**)&p_out, g_out);
    cudaGetSymbolAddress((void**)&p_s1,  g_s1);
    cudaGetSymbolAddress((void**)&p_s2,  g_s2);
    cudaGetSymbolAddress((void**)&p_s3,  g_s3);
    cudaGetSymbolAddress((void**)&p_sc,  g_scale);
    cudaGetSymbolAddress((void**)&p_sh,  g_shift);

    const int TB = 256;
    // graph build
    k_init <<<(Nn + TB - 1) / TB, TB>>>();
    k_count<<<(Ee + TB - 1) / TB, TB>>>(ei);
    k_dinv <<<(Nn + TB - 1) / TB, TB>>>();
    k_scan1<<<SCB, 1024>>>();
    k_scan2<<<1, 64>>>();
    k_scan3<<<(Nn + TB - 1) / TB, TB>>>();
    k_fill <<<(Ee + TB - 1) / TB, TB>>>(ei);

    int gP128 = (Nn + 3) / 4;
    int gGemm = (Nn + BM - 1) / BM;      // 391
    int g12   = (Nn + 31) / 32;          // 1563

    // layer 1 (F=3)
    k_prop3<<<(Nn + TB - 1) / TB, TB>>>(x, nullptr, p_s1);
    k_prop3<<<(Nn + TB - 1) / TB, TB>>>(p_s1, x, p_s2);
    k_prop3<<<(Nn + TB - 1) / TB, TB>>>(p_s2, p_s1, p_s3);
    k_gemm12<<<g12, Hd>>>(x, p_s1, p_s2, p_s3, W1, b1, p_out);
    k_bnfin<<<1, Hd>>>(g1, be1, g12);

    // layer 2 (props consume BN(h) via fused scale/shift)
    k_prop128<<<gP128, 128>>>(p_out, nullptr, p_t1, p_sc, p_sh, 1);
    k_prop128<<<gP128, 128>>>(p_t1, p_out, p_t2, p_sc, p_sh, 2);
    k_prop128<<<gP128, 128>>>(p_t2, p_t1, p_t3, nullptr, nullptr, 0);
    k_gemm_mma<<<gGemm, 256>>>(p_out, p_t1, p_t2, p_t3, W2, b2, p_out, p_sc, p_sh, 1);
    k_bnfin<<<1, Hd>>>(g2, be2, gGemm);

    // layer 3
    k_prop128<<<gP128, 128>>>(p_out, nullptr, p_t1, p_sc, p_sh, 1);
    k_prop128<<<gP128, 128>>>(p_t1, p_out, p_t2, p_sc, p_sh, 2);
    k_prop128<<<gP128, 128>>>(p_t2, p_t1, p_t3, nullptr, nullptr, 0);
    k_gemm_mma<<<gGemm, 256>>>(p_out, p_t1, p_t2, p_t3, W3, b3, p_out, p_sc, p_sh, 2);
    k_bnfin<<<1, Hd>>>(g3, be3, gGemm);

    // layer 4: props + GEMM with fused row-normalize, straight to d_out
    k_prop128<<<gP128, 128>>>(p_out, nullptr, p_t1, p_sc, p_sh, 1);
    k_prop128<<<gP128, 128>>>(p_t1, p_out, p_t2, p_sc, p_sh, 2);
    k_prop128<<<gP128, 128>>>(p_t2, p_t1, p_t3, nullptr, nullptr, 0);
    k_gemm_mma<<<gGemm, 256>>>(p_out, p_t1, p_t2, p_t3, W4, b4, (float*)d_out,
                               p_sc, p_sh, 0);
}